// round 7
// baseline (speedup 1.0000x reference)
#include <cuda_runtime.h>

// Problem constants (fixed by setup_inputs)
#define B_    4
#define C_    256
#define H_    256
#define W_    512
#define FS    14
#define NP    (FS*FS)        // 196
#define NROI  400            // B * MAXLOAD
#define HW    (H_*W_)        // 131072
#define HB    (B_*H_)        // 1024 stacked rows
#define CH    8              // channels per block (one per warp)
#define NCQ   (C_/CH)        // 32 channel slabs

#define THREADS 256
#define NW4MAX  130          // max float4 words per row span (<=129) + pad

static const long OUT_MAIN = (long)NROI * C_ * NP;        // 20,070,400
#define MAIN_BLOCKS (NCQ * NROI * FS)                     // 179,200

// coordinate pipeline (exactly as reference), x axis
__device__ __forceinline__ float sample_px(float j, float scalex, float biasx)
{
    float gridx = (j * (1.0f / 13.0f) * scalex + biasx) * 0.25f;
    float gx = (gridx * (1.0f / (W_ - 1)) - 0.5f) * 2.0f;
    float px = ((gx + 1.0f) * (float)W_ - 1.0f) * 0.5f;
    return fminf(fmaxf(px, 0.0f), (float)(W_ - 1));
}

__global__ __launch_bounds__(THREADS)
void pooler_stage_kernel(const float* __restrict__ feat,
                         const float* __restrict__ rois,
                         float*       __restrict__ out,
                         long out_size)
{
    __shared__ __align__(16) float tile[CH][2][NW4MAX * 4];

    const int blk = blockIdx.x;
    const int tid = threadIdx.x;

    // Tail: val_bind = repeat(arange(B), MAXLOAD) appended after main output.
    if (blk >= MAIN_BLOCKS) {
        long k   = (long)(blk - MAIN_BLOCKS) * THREADS + tid;
        long idx = OUT_MAIN + k;
        if (idx < out_size) out[idx] = (float)((int)(k / 100));
        return;
    }

    // blk = cq*5600 + n*14 + i   (cq slowest -> channel-slab L2 behavior)
    const int i    = blk % FS;
    const int rest = blk / FS;
    const int n    = rest % NROI;
    const int cq   = rest / NROI;
    const int c0   = cq * CH;
    const int b    = n / 100;                   // roi's batch

    const float4 r = reinterpret_cast<const float4*>(rois)[n];
    const float scalex = r.z - r.x;

    // y coordinates (constant per block)
    float scaley = r.w - r.y;
    float biasy  = r.y + (float)b * 1024.0f;    // image_height
    float gridy  = ((float)i * (1.0f / 13.0f) * scaley + biasy) * 0.25f;
    float gy = (gridy * (1.0f / (HB - 1)) - 0.5f) * 2.0f;
    float py = ((gy + 1.0f) * (float)HB - 1.0f) * 0.5f;
    py = fminf(fmaxf(py, 0.0f), (float)(HB - 1));
    float y0f = floorf(py);
    float wy  = py - y0f;
    int y0 = (int)y0f;
    int y1 = min(y0 + 1, HB - 1);

    // x span endpoints (every thread computes; cheap, avoids syncs)
    int xs = (int)floorf(sample_px(0.0f,  scalex, r.x));           // x0 at j=0
    int xe = min((int)floorf(sample_px(13.0f, scalex, r.x)) + 1, W_ - 1);
    int ws  = xs >> 2;
    int nw4 = (xe >> 2) - ws + 1;               // float4 words per row (<=129)

    // staging: warp w stages channel c0+w, rows y0 & y1, coalesced float4
    {
        const int w    = tid >> 5;              // warp id = channel lane
        const int lane = tid & 31;
        const float4* f4 = reinterpret_cast<const float4*>(feat);
        int ch = c0 + w;
        int rb0 = ((((y0 >> 8) * C_ + ch) * HW + (y0 & 255) * W_) >> 2) + ws;
        int rb1 = ((((y1 >> 8) * C_ + ch) * HW + (y1 & 255) * W_) >> 2) + ws;
        float4* t0 = reinterpret_cast<float4*>(tile[w][0]);
        float4* t1 = reinterpret_cast<float4*>(tile[w][1]);
        for (int word = lane; word < nw4; word += 32) {
            t0[word] = __ldg(f4 + rb0 + word);
            t1[word] = __ldg(f4 + rb1 + word);
        }
    }
    __syncthreads();

    // compute: 8 channels x 14 samples; thread (cl = tid>>4, j = tid&15)
    if (tid < CH * 16) {
        int cl = tid >> 4;
        int j  = tid & 15;
        if (j < FS) {
            float px = sample_px((float)j, scalex, r.x);
            float x0f = floorf(px);
            float wx  = px - x0f;
            int x0 = (int)x0f;
            int x1 = min(x0 + 1, W_ - 1);
            int o0 = x0 - (ws << 2);
            int o1 = x1 - (ws << 2);
            float f00 = tile[cl][0][o0];
            float f01 = tile[cl][0][o1];
            float f10 = tile[cl][1][o0];
            float f11 = tile[cl][1][o1];
            float omwx = 1.0f - wx;
            float omwy = 1.0f - wy;
            float v = (f00 * omwx + f01 * wx) * omwy
                    + (f10 * omwx + f11 * wx) * wy;
            out[((long)(n * C_ + c0 + cl)) * NP + i * FS + j] = v;
        }
    }
}

extern "C" void kernel_launch(void* const* d_in, const int* in_sizes, int n_in,
                              void* d_out, int out_size)
{
    const float* feat = (const float*)d_in[0];
    const float* rois = (const float*)d_in[1];
    float* out = (float*)d_out;

    long tail = (long)out_size - OUT_MAIN;
    int tail_blocks = tail > 0 ? (int)((tail + THREADS - 1) / THREADS) : 0;

    pooler_stage_kernel<<<MAIN_BLOCKS + tail_blocks, THREADS>>>(
        feat, rois, out, (long)out_size);
}

// round 8
// speedup vs baseline: 3.6616x; 3.6616x over previous
#include <cuda_runtime.h>

// Problem constants (fixed by setup_inputs)
#define B_    4
#define C_    256
#define H_    256
#define W_    512
#define FS    14
#define NP    (FS*FS)        // 196
#define NROI  400            // B * MAXLOAD
#define HW    (H_*W_)        // 131072
#define HB    (B_*H_)        // 1024 stacked rows
#define KCH   4              // channels per thread
#define NCQ   (C_/KCH)       // 64 channel groups

#define THREADS 256

static const long OUT_MAIN   = (long)NROI * C_ * NP;      // 20,070,400
#define MAIN_THREADS (NROI * NCQ * NP)                    // 5,017,600
#define MAIN_BLOCKS  (MAIN_THREADS / THREADS)             // 19,600 (exact)

// select element s (0..3) of q
__device__ __forceinline__ float pick(float4 q, int s)
{
    float v = (s == 0) ? q.x : ((s == 1) ? q.y : ((s == 2) ? q.z : q.w));
    return v;
}

__global__ __launch_bounds__(THREADS)
void pooler_f4_kernel(const float* __restrict__ feat,
                      const float* __restrict__ rois,
                      float*       __restrict__ out,
                      long out_size)
{
    int t = blockIdx.x * THREADS + threadIdx.x;

    // Tail: val_bind = repeat(arange(B), MAXLOAD) appended after main output.
    if (t >= MAIN_THREADS) {
        long k   = (long)(t - MAIN_THREADS);
        long idx = OUT_MAIN + k;
        if (idx < out_size) out[idx] = (float)((int)(k / 100));
        return;
    }

    // Decode: p fastest (warp coalescing), n middle, cq SLOWEST
    // (channel-slab ordering: a wave covers all ROIs in a narrow slab -> L2 reuse)
    int p  = t % NP;
    int q  = t / NP;
    int n  = q % NROI;
    int cq = q / NROI;
    int c  = cq * KCH;
    int i  = p / FS;
    int j  = p - i * FS;
    int b  = n / 100;                         // roi's batch

    const float4 r = reinterpret_cast<const float4*>(rois)[n];
    const float inv13 = 1.0f / 13.0f;

    float scalex = r.z - r.x;
    float scaley = r.w - r.y;
    float biasy  = r.y + (float)b * 1024.0f;  // image_height

    float gridx = ((float)j * inv13 * scalex + r.x)  * 0.25f;  // /shrink_scale
    float gridy = ((float)i * inv13 * scaley + biasy) * 0.25f;

    // normalized-grid round trip, exactly as reference
    float gx = (gridx * (1.0f / (W_ - 1)) - 0.5f) * 2.0f;
    float gy = (gridy * (1.0f / (HB - 1)) - 0.5f) * 2.0f;
    float px = ((gx + 1.0f) * (float)W_ - 1.0f) * 0.5f;
    float py = ((gy + 1.0f) * (float)HB - 1.0f) * 0.5f;
    px = fminf(fmaxf(px, 0.0f), (float)(W_ - 1));
    py = fminf(fmaxf(py, 0.0f), (float)(HB - 1));

    float x0f = floorf(px);
    float y0f = floorf(py);
    float wx  = px - x0f;
    float wy  = py - y0f;
    int x0 = (int)x0f;
    int y0 = (int)y0f;
    int x1 = min(x0 + 1, W_ - 1);
    int y1 = min(y0 + 1, HB - 1);

    // feats view (C, B*H, W); element indices fit in int32 (max ~134M)
    int a0 = ((y0 >> 8) * C_ + c) * HW + (y0 & 255) * W_;
    int a1 = ((y1 >> 8) * C_ + c) * HW + (y1 & 255) * W_;

    // Aligned float4 covering x0 (and x0+1 unless x0%4==3): one 32B sector,
    // one L1 line per lane instead of two scattered LDG.32.
    int xb  = x0 & ~3;                 // 16B-aligned element base
    int sel = x0 & 3;
    bool far = (sel == 3);             // x1 falls outside the float4

    const float4* f4 = reinterpret_cast<const float4*>(feat);
    float4 q0[KCH], q1[KCH];
#pragma unroll
    for (int k = 0; k < KCH; k++)
        q0[k] = __ldg(f4 + ((a0 + k * HW + xb) >> 2));
#pragma unroll
    for (int k = 0; k < KCH; k++)
        q1[k] = __ldg(f4 + ((a1 + k * HW + xb) >> 2));

    // Predicated edge loads (25% of lanes active on average)
    float e0[KCH], e1[KCH];
#pragma unroll
    for (int k = 0; k < KCH; k++)
        e0[k] = far ? __ldg(feat + a0 + k * HW + x1) : 0.0f;
#pragma unroll
    for (int k = 0; k < KCH; k++)
        e1[k] = far ? __ldg(feat + a1 + k * HW + x1) : 0.0f;

    float omwx = 1.0f - wx;
    float omwy = 1.0f - wy;
    long ob = ((long)(n * C_ + c)) * NP + p;
#pragma unroll
    for (int k = 0; k < KCH; k++) {
        float f00 = pick(q0[k], sel);
        float f10 = pick(q1[k], sel);
        float f01 = far ? e0[k] : pick(q0[k], sel + 1);
        float f11 = far ? e1[k] : pick(q1[k], sel + 1);
        float v = (f00 * omwx + f01 * wx) * omwy
                + (f10 * omwx + f11 * wx) * wy;
        out[ob + (long)k * NP] = v;
    }
}

extern "C" void kernel_launch(void* const* d_in, const int* in_sizes, int n_in,
                              void* d_out, int out_size)
{
    const float* feat = (const float*)d_in[0];
    const float* rois = (const float*)d_in[1];
    float* out = (float*)d_out;

    long tail = (long)out_size - OUT_MAIN;
    int tail_blocks = tail > 0 ? (int)((tail + THREADS - 1) / THREADS) : 0;

    pooler_f4_kernel<<<MAIN_BLOCKS + tail_blocks, THREADS>>>(
        feat, rois, out, (long)out_size);
}